// round 6
// baseline (speedup 1.0000x reference)
#include <cuda_runtime.h>

#define BATCH 4
#define SEQ   2048
#define EMB   1024
#define NH    16
#define HD    64

// Scratch (allocation-free rule: __device__ globals). ~134 MB total.
__device__ float g_q[(size_t)BATCH * NH * SEQ * HD];
__device__ float g_k[(size_t)BATCH * NH * SEQ * HD];
__device__ float g_v[(size_t)BATCH * NH * SEQ * HD];
__device__ float g_attn[(size_t)BATCH * SEQ * EMB];

// ---------------------------------------------------------------------------
// Generic fp32 GEMM tile: C[128 x 64] += A[128 x K] * B[K x 64] (+ bias)
// 256 threads, each computes 8x4. A staged transposed (As[k][m], 132-stride
// padding -> 2-way STS conflicts only); B staged row-major for float4 reads.
// ---------------------------------------------------------------------------
__device__ __forceinline__ void gemm_tile(
    const float* __restrict__ A, int lda,
    const float* __restrict__ Bm, int ldb,
    float* __restrict__ C, int ldc,
    const float* __restrict__ bias, int K)
{
    __shared__ float As[16][132];   // [k][m]
    __shared__ float Bs[16][64];    // [k][n]

    const int tid = threadIdx.x;
    const int ty = tid >> 4;        // 0..15 -> 8 rows each
    const int tx = tid & 15;        // 0..15 -> 4 cols each

    float acc[8][4];
#pragma unroll
    for (int i = 0; i < 8; ++i)
#pragma unroll
        for (int j = 0; j < 4; ++j) acc[i][j] = 0.f;

    const int nkt = K >> 4;
    for (int kt = 0; kt < nkt; ++kt) {
        // Stage A: 128x16 = 512 float4, 2 per thread, transposed store.
#pragma unroll
        for (int u = 0; u < 2; ++u) {
            int idx = tid + u * 256;
            int row = idx >> 2;
            int kq  = idx & 3;
            float4 va = *(const float4*)(A + (size_t)row * lda + kt * 16 + kq * 4);
            As[kq * 4 + 0][row] = va.x;
            As[kq * 4 + 1][row] = va.y;
            As[kq * 4 + 2][row] = va.z;
            As[kq * 4 + 3][row] = va.w;
        }
        // Stage B: 16x64 = 256 float4, 1 per thread.
        {
            int row = tid >> 4;
            int cq  = tid & 15;
            *(float4*)&Bs[row][cq * 4] =
                *(const float4*)(Bm + (size_t)(kt * 16 + row) * ldb + cq * 4);
        }
        __syncthreads();

#pragma unroll
        for (int k = 0; k < 16; ++k) {
            float a[8], b4[4];
            *(float4*)&a[0] = *(const float4*)&As[k][ty * 8];
            *(float4*)&a[4] = *(const float4*)&As[k][ty * 8 + 4];
            *(float4*)&b4[0] = *(const float4*)&Bs[k][tx * 4];
#pragma unroll
            for (int i = 0; i < 8; ++i)
#pragma unroll
                for (int j = 0; j < 4; ++j)
                    acc[i][j] = fmaf(a[i], b4[j], acc[i][j]);
        }
        __syncthreads();
    }

    float bb[4] = {0.f, 0.f, 0.f, 0.f};
    if (bias) {
        bb[0] = bias[tx * 4 + 0];
        bb[1] = bias[tx * 4 + 1];
        bb[2] = bias[tx * 4 + 2];
        bb[3] = bias[tx * 4 + 3];
    }
#pragma unroll
    for (int i = 0; i < 8; ++i) {
        float4 o;
        o.x = acc[i][0] + bb[0];
        o.y = acc[i][1] + bb[1];
        o.z = acc[i][2] + bb[2];
        o.w = acc[i][3] + bb[3];
        *(float4*)(C + (size_t)(ty * 8 + i) * ldc + tx * 4) = o;
    }
}

// ---------------------------------------------------------------------------
// QKV projection: grid (64, 16 heads, 3={q,k,v}); writes [B,H,S,64] scratch.
// ---------------------------------------------------------------------------
__global__ __launch_bounds__(256) void qkv_kernel(
    const float* __restrict__ x,
    const float* __restrict__ Wq,
    const float* __restrict__ Wk,
    const float* __restrict__ Wv)
{
    const int h = blockIdx.y;
    const int which = blockIdx.z;
    const float* W   = (which == 0) ? Wq : (which == 1) ? Wk : Wv;
    float*       out = (which == 0) ? g_q : (which == 1) ? g_k : g_v;

    const int m0 = blockIdx.x * 128;        // 128 divides SEQ -> no batch crossing
    const int b  = m0 / SEQ;
    const int sr = m0 % SEQ;

    const float* A  = x + (size_t)m0 * EMB;
    const float* Bm = W + (size_t)h * EMB * HD;   // B[k][d] = W[h][k][d], ldb=64
    float* C = out + (((size_t)b * NH + h) * SEQ + sr) * HD;

    gemm_tile(A, EMB, Bm, HD, C, HD, nullptr, EMB);
}

// ---------------------------------------------------------------------------
// Causal flash attention, fp32. grid (S/64, H, B), 256 threads.
// Q 64x64 pre-scaled; K^T staged into Kt with an XOR granule swizzle:
//   element (kk, n) lives at word  kk*64 + (((n>>2) ^ (kk>>2)) << 2) + (n&3)
// Store side (thread owns n, rows kk=4f+c, f=kk>>2): granules (n>>2)^f are 16
// distinct values per half-warp -> ~2-way STS conflicts (was 16-way).
// Read side (lane tx, row kk): granule tx ^ (kk>>2), float4-aligned,
// 16 distinct -> conflict-free.
// P overlays Kt (straight indexing, separate phase). Static smem = 48 KB.
// ---------------------------------------------------------------------------
__global__ __launch_bounds__(256) void attn_kernel()
{
    __shared__ float Qs[64 * 64];
    __shared__ float Kt[64 * 64];   // scores phase: swizzled K^T; then P
    __shared__ float Vs[64 * 64];

    const int qb = blockIdx.x;
    const int h  = blockIdx.y;
    const int b  = blockIdx.z;
    const int bh = b * NH + h;

    const float* Q  = g_q + (size_t)bh * SEQ * HD;
    const float* Kp = g_k + (size_t)bh * SEQ * HD;
    const float* Vp = g_v + (size_t)bh * SEQ * HD;

    const int tid = threadIdx.x;
    const int ty  = tid >> 4;
    const int tx  = tid & 15;
    const int q0  = qb * 64;

    // Load Q tile, fold in softmax scale 1/sqrt(64) = 0.125
    for (int i = tid; i < 1024; i += 256) {
        int r = i >> 4, f = i & 15;
        float4 v = *(const float4*)(Q + (size_t)(q0 + r) * HD + f * 4);
        v.x *= 0.125f; v.y *= 0.125f; v.z *= 0.125f; v.w *= 0.125f;
        *(float4*)&Qs[r * 64 + f * 4] = v;
    }

    float acc[4][4];
    float mi[4], li[4];
#pragma unroll
    for (int r = 0; r < 4; ++r) {
        mi[r] = -1e30f; li[r] = 0.f;
#pragma unroll
        for (int c = 0; c < 4; ++c) acc[r][c] = 0.f;
    }

    for (int j = 0; j <= qb; ++j) {
        __syncthreads();   // prior P@V reads of Kt/Vs complete (also covers Qs init)

        // Stage K (swizzled transpose) and V (row-major)
        for (int i = tid; i < 1024; i += 256) {
            int n = i >> 4, f = i & 15;
            float4 kv = *(const float4*)(Kp + (size_t)(j * 64 + n) * HD + f * 4);
            int go = (((n >> 2) ^ f) << 2) + (n & 3);   // swizzled column word
            Kt[(f * 4 + 0) * 64 + go] = kv.x;
            Kt[(f * 4 + 1) * 64 + go] = kv.y;
            Kt[(f * 4 + 2) * 64 + go] = kv.z;
            Kt[(f * 4 + 3) * 64 + go] = kv.w;
            *(float4*)&Vs[n * 64 + f * 4] =
                *(const float4*)(Vp + (size_t)(j * 64 + n) * HD + f * 4);
        }
        __syncthreads();

        // S = Q K^T (pre-scaled)
        float s[4][4];
#pragma unroll
        for (int r = 0; r < 4; ++r)
#pragma unroll
            for (int c = 0; c < 4; ++c) s[r][c] = 0.f;

#pragma unroll
        for (int k = 0; k < 64; k += 4) {
            float q4[4][4], k4[4][4];
#pragma unroll
            for (int r = 0; r < 4; ++r)
                *(float4*)&q4[r][0] = *(const float4*)&Qs[(ty * 4 + r) * 64 + k];
#pragma unroll
            for (int t = 0; t < 4; ++t) {
                int kk = k + t;
                *(float4*)&k4[t][0] =
                    *(const float4*)&Kt[kk * 64 + ((tx ^ (kk >> 2)) << 2)];
            }
#pragma unroll
            for (int r = 0; r < 4; ++r)
#pragma unroll
                for (int t = 0; t < 4; ++t)
#pragma unroll
                    for (int c = 0; c < 4; ++c)
                        s[r][c] = fmaf(q4[r][t], k4[t][c], s[r][c]);
        }

        // Causal mask: only the diagonal block needs it
        if (j == qb) {
#pragma unroll
            for (int r = 0; r < 4; ++r)
#pragma unroll
                for (int c = 0; c < 4; ++c)
                    if (tx * 4 + c > ty * 4 + r) s[r][c] = -1e30f;
        }

        __syncthreads();   // everyone done reading Kt before it becomes P

        // Online softmax; lanes with the same ty form a 16-wide row group.
#pragma unroll
        for (int r = 0; r < 4; ++r) {
            float rm = fmaxf(fmaxf(s[r][0], s[r][1]), fmaxf(s[r][2], s[r][3]));
#pragma unroll
            for (int off = 8; off >= 1; off >>= 1)
                rm = fmaxf(rm, __shfl_xor_sync(0xffffffffu, rm, off, 16));
            float mnew  = fmaxf(mi[r], rm);
            float alpha = __expf(mi[r] - mnew);
            mi[r] = mnew;

            float ls = 0.f;
#pragma unroll
            for (int c = 0; c < 4; ++c) {
                s[r][c] = __expf(s[r][c] - mnew);
                ls += s[r][c];
            }
#pragma unroll
            for (int off = 8; off >= 1; off >>= 1)
                ls += __shfl_xor_sync(0xffffffffu, ls, off, 16);
            li[r] = li[r] * alpha + ls;
#pragma unroll
            for (int c = 0; c < 4; ++c) acc[r][c] *= alpha;

            *(float4*)&Kt[(ty * 4 + r) * 64 + tx * 4] = *(float4*)&s[r][0];  // P
        }
        __syncthreads();

        // O += P @ V
#pragma unroll
        for (int k = 0; k < 64; k += 4) {
            float p4[4][4], v4[4][4];
#pragma unroll
            for (int r = 0; r < 4; ++r)
                *(float4*)&p4[r][0] = *(const float4*)&Kt[(ty * 4 + r) * 64 + k];
#pragma unroll
            for (int t = 0; t < 4; ++t)
                *(float4*)&v4[t][0] = *(const float4*)&Vs[(k + t) * 64 + tx * 4];
#pragma unroll
            for (int r = 0; r < 4; ++r)
#pragma unroll
                for (int t = 0; t < 4; ++t)
#pragma unroll
                    for (int c = 0; c < 4; ++c)
                        acc[r][c] = fmaf(p4[r][t], v4[t][c], acc[r][c]);
        }
    }

    // Normalize and write concatenated-head layout [B,S,E]
#pragma unroll
    for (int r = 0; r < 4; ++r) {
        float inv = 1.f / li[r];
        float4 o = make_float4(acc[r][0] * inv, acc[r][1] * inv,
                               acc[r][2] * inv, acc[r][3] * inv);
        *(float4*)&g_attn[((size_t)b * SEQ + q0 + ty * 4 + r) * EMB + h * HD + tx * 4] = o;
    }
}

// ---------------------------------------------------------------------------
// Output projection: out = g_attn @ Wp + bp. grid (64, 16).
// ---------------------------------------------------------------------------
__global__ __launch_bounds__(256) void proj_kernel(
    const float* __restrict__ Wp,
    const float* __restrict__ bp,
    float* __restrict__ out)
{
    const int m0 = blockIdx.x * 128;
    const int n0 = blockIdx.y * 64;
    gemm_tile(g_attn + (size_t)m0 * EMB, EMB,
              Wp + n0, EMB,
              out + (size_t)m0 * EMB + n0, EMB,
              bp + n0, EMB);
}

// ---------------------------------------------------------------------------
extern "C" void kernel_launch(void* const* d_in, const int* in_sizes, int n_in,
                              void* d_out, int out_size)
{
    const float* x  = (const float*)d_in[0];
    const float* Wq = (const float*)d_in[1];
    const float* Wk = (const float*)d_in[2];
    const float* Wv = (const float*)d_in[3];
    const float* Wp = (const float*)d_in[4];
    const float* bp = (const float*)d_in[5];
    float* out = (float*)d_out;

    dim3 g1(BATCH * SEQ / 128, NH, 3);
    qkv_kernel<<<g1, 256>>>(x, Wq, Wk, Wv);

    dim3 g2(SEQ / 64, NH, BATCH);
    attn_kernel<<<g2, 256>>>();

    dim3 g3(BATCH * SEQ / 128, EMB / 64);
    proj_kernel<<<g3, 256>>>(Wp, bp, out);
}

// round 9
// speedup vs baseline: 1.5194x; 1.5194x over previous
#include <cuda_runtime.h>
#include <cuda_bf16.h>
#include <cstdint>

#define BATCH 4
#define SEQ   2048
#define EMB   1024
#define NH    16
#define HD    64

// ---------------------------------------------------------------------------
// Scratch (__device__ globals; no allocation anywhere).
// NOTE: these are ONLY referenced from device code — passing a __device__
// symbol as a host-side kernel argument passes the host shadow address (the
// R7/R8 bug).
// ---------------------------------------------------------------------------
__device__ float g_q[(size_t)BATCH * NH * SEQ * HD];
__device__ float g_k[(size_t)BATCH * NH * SEQ * HD];
__device__ float g_v[(size_t)BATCH * NH * SEQ * HD];
__device__ float g_attn[(size_t)BATCH * SEQ * EMB];

// bf16 hi/lo split operands (16-byte aligned for uint4 loads)
__device__ __align__(16) __nv_bfloat16 g_xhi[(size_t)BATCH * SEQ * EMB];
__device__ __align__(16) __nv_bfloat16 g_xlo[(size_t)BATCH * SEQ * EMB];
__device__ __align__(16) __nv_bfloat16 g_ahi[(size_t)BATCH * SEQ * EMB];
__device__ __align__(16) __nv_bfloat16 g_alo[(size_t)BATCH * SEQ * EMB];
__device__ __align__(16) __nv_bfloat16 g_bqkv_hi[(size_t)3 * NH * HD * EMB]; // [3072][1024]
__device__ __align__(16) __nv_bfloat16 g_bqkv_lo[(size_t)3 * NH * HD * EMB];
__device__ __align__(16) __nv_bfloat16 g_bp_hi[(size_t)EMB * EMB];           // [1024][1024] = Wp^T
__device__ __align__(16) __nv_bfloat16 g_bp_lo[(size_t)EMB * EMB];

// ---------------------------------------------------------------------------
// Split-precision conversion kernels (device globals referenced in-kernel)
// ---------------------------------------------------------------------------
__device__ __forceinline__ void split1(float v, __nv_bfloat16& h, __nv_bfloat16& l) {
    h = __float2bfloat16(v);
    l = __float2bfloat16(v - __bfloat162float(h));
}

union BF4 { __nv_bfloat16 b[4]; uint2 u; };

__global__ void split_x(const float* __restrict__ in)   // x -> g_xhi/g_xlo
{
    int i = blockIdx.x * 256 + threadIdx.x;             // float4 index
    float4 v = ((const float4*)in)[i];
    BF4 hh, ll;
    split1(v.x, hh.b[0], ll.b[0]);
    split1(v.y, hh.b[1], ll.b[1]);
    split1(v.z, hh.b[2], ll.b[2]);
    split1(v.w, hh.b[3], ll.b[3]);
    ((uint2*)g_xhi)[i] = hh.u;
    ((uint2*)g_xlo)[i] = ll.u;
}

__global__ void split_attn()                            // g_attn -> g_ahi/g_alo
{
    int i = blockIdx.x * 256 + threadIdx.x;
    float4 v = ((const float4*)g_attn)[i];
    BF4 hh, ll;
    split1(v.x, hh.b[0], ll.b[0]);
    split1(v.y, hh.b[1], ll.b[1]);
    split1(v.z, hh.b[2], ll.b[2]);
    split1(v.w, hh.b[3], ll.b[3]);
    ((uint2*)g_ahi)[i] = hh.u;
    ((uint2*)g_alo)[i] = ll.u;
}

// Gather W{q,k,v}[h][e][d] -> Bqkv[n][e], n = which*1024 + h*64 + d
__global__ void conv_wqkv(const float* __restrict__ Wq,
                          const float* __restrict__ Wk,
                          const float* __restrict__ Wv)
{
    int n = blockIdx.x;
    int which = n >> 10, h = (n >> 6) & 15, d = n & 63;
    const float* W = (which == 0) ? Wq : (which == 1) ? Wk : Wv;
    for (int e = threadIdx.x; e < EMB; e += 256) {
        float v = W[((size_t)h * EMB + e) * HD + d];
        __nv_bfloat16 hh, ll;
        split1(v, hh, ll);
        g_bqkv_hi[(size_t)n * EMB + e] = hh;
        g_bqkv_lo[(size_t)n * EMB + e] = ll;
    }
}

// Transpose Wp[k][n] -> Bp[n][k], split hi/lo
__global__ void conv_wp(const float* __restrict__ Wp)
{
    __shared__ float t[32][33];
    int n0 = blockIdx.x * 32, k0 = blockIdx.y * 32;
    for (int r = threadIdx.y; r < 32; r += 8)
        t[r][threadIdx.x] = Wp[(size_t)(k0 + r) * EMB + n0 + threadIdx.x];
    __syncthreads();
    for (int r = threadIdx.y; r < 32; r += 8) {
        float v = t[threadIdx.x][r];   // = Wp[k0+tx][n0+r]
        __nv_bfloat16 hh, ll;
        split1(v, hh, ll);
        g_bp_hi[(size_t)(n0 + r) * EMB + k0 + threadIdx.x] = hh;
        g_bp_lo[(size_t)(n0 + r) * EMB + k0 + threadIdx.x] = ll;
    }
}

// ---------------------------------------------------------------------------
// HMMA helpers (sm_80-era PTX; compiles for base compute_103 target)
// ---------------------------------------------------------------------------
__device__ __forceinline__ uint32_t smem_u32(const void* p) {
    uint32_t a;
    asm("{ .reg .u64 t; cvta.to.shared.u64 t, %1; cvt.u32.u64 %0, t; }" : "=r"(a) : "l"(p));
    return a;
}
__device__ __forceinline__ void ldsm_x4(uint32_t* r, uint32_t addr) {
    asm volatile("ldmatrix.sync.aligned.m8n8.x4.shared.b16 {%0,%1,%2,%3}, [%4];"
        : "=r"(r[0]), "=r"(r[1]), "=r"(r[2]), "=r"(r[3]) : "r"(addr));
}
__device__ __forceinline__ void mma_bf16(float* c, const uint32_t* a,
                                         uint32_t b0, uint32_t b1) {
    asm volatile("mma.sync.aligned.m16n8k16.row.col.f32.bf16.bf16.f32 "
        "{%0,%1,%2,%3}, {%4,%5,%6,%7}, {%8,%9}, {%0,%1,%2,%3};"
        : "+f"(c[0]), "+f"(c[1]), "+f"(c[2]), "+f"(c[3])
        : "r"(a[0]), "r"(a[1]), "r"(a[2]), "r"(a[3]), "r"(b0), "r"(b1));
}

// ---------------------------------------------------------------------------
// Split-precision bf16 HMMA GEMM: D[128x64] = A[128x1024] * B^T (B given [N][K])
// D = Ah*Bh + Ah*Bl + Al*Bh, fp32 accum. 256 threads, 8 warps = 4m x 2n of
// 32x32 warp tiles (mma.m16n8k16). K staged in chunks of 64 bf16; smem row
// stride 144B. Operands selected from device globals by `mode`:
//   mode 0: A=g_xhi/lo, B=g_bqkv_hi/lo, scatter into g_q/g_k/g_v [B,H,S,64]
//   mode 1: A=g_ahi/lo, B=g_bp_hi/lo, +bias, row-major out
// ---------------------------------------------------------------------------
#define RS 72                       // smem row stride in bf16 (144 B)
#define OFF_AH 0
#define OFF_AL (128 * RS)
#define OFF_BH (256 * RS)
#define OFF_BL (256 * RS + 64 * RS)
#define GEMM_SMEM ((256 * RS + 128 * RS) * 2)   // 55296 B

__global__ __launch_bounds__(256) void hmma_gemm(
    const float* __restrict__ bias,
    float* __restrict__ outp, int mode)
{
    extern __shared__ __align__(16) __nv_bfloat16 sm[];
    const int tid = threadIdx.x, wid = tid >> 5, lane = tid & 31;
    const int wm = wid >> 1, wn = wid & 1;          // 4 x 2 warp grid
    const int m0 = blockIdx.x * 128, n0 = blockIdx.y * 64;

    // Device-side operand selection (device addresses — the R8 fix)
    const __nv_bfloat16* __restrict__ Ahi = (mode == 0) ? g_xhi : g_ahi;
    const __nv_bfloat16* __restrict__ Alo = (mode == 0) ? g_xlo : g_alo;
    const __nv_bfloat16* __restrict__ Bhi = (mode == 0) ? g_bqkv_hi : g_bp_hi;
    const __nv_bfloat16* __restrict__ Blo = (mode == 0) ? g_bqkv_lo : g_bp_lo;

    float acc[2][4][4];
#pragma unroll
    for (int mt = 0; mt < 2; ++mt)
#pragma unroll
        for (int nt = 0; nt < 4; ++nt)
#pragma unroll
            for (int i = 0; i < 4; ++i) acc[mt][nt][i] = 0.f;

    // Per-lane ldmatrix row addresses.
    // A (x4, tile mt): matrices = (rows0-7,k0-7),(rows8-15,k0-7),(rows0-7,k8-15),(rows8-15,k8-15)
    const uint32_t a_row = wm * 32 + ((lane >> 3) & 1) * 8 + (lane & 7);
    const uint32_t a_kof = ((lane >> 4) & 1) * 8;
    // B (x4, group g16): matrices = (n0-7,k0-7),(n0-7,k8-15),(n8-15,k0-7),(n8-15,k8-15)
    const uint32_t b_row = wn * 32 + ((lane >> 4) & 1) * 8 + (lane & 7);
    const uint32_t b_kof = ((lane >> 3) & 1) * 8;
    const uint32_t sb = smem_u32(sm);
    const uint32_t aA = sb + (a_row * RS + a_kof) * 2;
    const uint32_t aB = sb + (b_row * RS + b_kof) * 2;

    for (int kt = 0; kt < 16; ++kt) {
        __syncthreads();
        // Stage A (128 rows x 64 bf16, hi+lo) and B (64 rows x 64, hi+lo)
#pragma unroll
        for (int t = 0; t < 4; ++t) {
            int i = tid + t * 256;
            int row = i >> 3, g = i & 7;
            size_t src = (size_t)(m0 + row) * 128 + kt * 8 + g;     // uint4 units
            uint32_t d = row * RS + g * 8;                           // bf16 units
            *(uint4*)(sm + OFF_AH + d) = ((const uint4*)Ahi)[src];
            *(uint4*)(sm + OFF_AL + d) = ((const uint4*)Alo)[src];
        }
#pragma unroll
        for (int t = 0; t < 2; ++t) {
            int i = tid + t * 256;
            int row = i >> 3, g = i & 7;
            size_t src = (size_t)(n0 + row) * 128 + kt * 8 + g;
            uint32_t d = row * RS + g * 8;
            *(uint4*)(sm + OFF_BH + d) = ((const uint4*)Bhi)[src];
            *(uint4*)(sm + OFF_BL + d) = ((const uint4*)Blo)[src];
        }
        __syncthreads();

#pragma unroll
        for (int ks = 0; ks < 4; ++ks) {
            uint32_t aH[2][4], aL[2][4], bH[2][4], bL[2][4];
#pragma unroll
            for (int mt = 0; mt < 2; ++mt) {
                uint32_t off = mt * (16 * RS * 2) + ks * 32;
                ldsm_x4(aH[mt], aA + OFF_AH * 2 + off);
                ldsm_x4(aL[mt], aA + OFF_AL * 2 + off);
            }
#pragma unroll
            for (int g16 = 0; g16 < 2; ++g16) {
                uint32_t off = g16 * (16 * RS * 2) + ks * 32;
                ldsm_x4(bH[g16], aB + OFF_BH * 2 + off);
                ldsm_x4(bL[g16], aB + OFF_BL * 2 + off);
            }
#pragma unroll
            for (int mt = 0; mt < 2; ++mt)
#pragma unroll
                for (int nt = 0; nt < 4; ++nt) {
                    uint32_t h0 = bH[nt >> 1][(nt & 1) * 2], h1 = bH[nt >> 1][(nt & 1) * 2 + 1];
                    uint32_t l0 = bL[nt >> 1][(nt & 1) * 2], l1 = bL[nt >> 1][(nt & 1) * 2 + 1];
                    mma_bf16(acc[mt][nt], aH[mt], h0, h1);
                    mma_bf16(acc[mt][nt], aH[mt], l0, l1);
                    mma_bf16(acc[mt][nt], aL[mt], h0, h1);
                }
        }
    }

    // Epilogue: thread holds rows (g, g+8), col pair (lane&3)*2 per (mt,nt)
    const int gr = lane >> 2, cp = (lane & 3) * 2;
#pragma unroll
    for (int mt = 0; mt < 2; ++mt)
#pragma unroll
        for (int nt = 0; nt < 4; ++nt) {
            int ng = n0 + wn * 32 + nt * 8 + cp;
#pragma unroll
            for (int half = 0; half < 2; ++half) {
                int m = m0 + wm * 32 + mt * 16 + gr + half * 8;
                float2 v = make_float2(acc[mt][nt][half * 2], acc[mt][nt][half * 2 + 1]);
                float* dst;
                if (mode == 1) {
                    v.x += bias[ng]; v.y += bias[ng + 1];
                    dst = outp + (size_t)m * EMB + ng;
                } else {
                    int which = ng >> 10, h = (ng >> 6) & 15, d = ng & 63;
                    int b = m >> 11, s = m & 2047;
                    float* base = (which == 0) ? g_q : (which == 1) ? g_k : g_v;
                    dst = base + (((size_t)b * NH + h) * SEQ + s) * HD + d;
                }
                *(float2*)dst = v;
            }
        }
}

// ---------------------------------------------------------------------------
// Causal flash attention, fp32 (unchanged from passing R6 kernel).
// ---------------------------------------------------------------------------
__global__ __launch_bounds__(256) void attn_kernel()
{
    __shared__ float Qs[64 * 64];
    __shared__ float Kt[64 * 64];   // swizzled K^T; then P
    __shared__ float Vs[64 * 64];

    const int qb = blockIdx.x;
    const int h  = blockIdx.y;
    const int b  = blockIdx.z;
    const int bh = b * NH + h;

    const float* Q  = g_q + (size_t)bh * SEQ * HD;
    const float* Kp = g_k + (size_t)bh * SEQ * HD;
    const float* Vp = g_v + (size_t)bh * SEQ * HD;

    const int tid = threadIdx.x;
    const int ty  = tid >> 4;
    const int tx  = tid & 15;
    const int q0  = qb * 64;

    for (int i = tid; i < 1024; i += 256) {
        int r = i >> 4, f = i & 15;
        float4 v = *(const float4*)(Q + (size_t)(q0 + r) * HD + f * 4);
        v.x *= 0.125f; v.y *= 0.125f; v.z *= 0.125f; v.w *= 0.125f;
        *(float4*)&Qs[r * 64 + f * 4] = v;
    }

    float acc[4][4];
    float mi[4], li[4];
#pragma unroll
    for (int r = 0; r < 4; ++r) {
        mi[r] = -1e30f; li[r] = 0.f;
#pragma unroll
        for (int c = 0; c < 4; ++c) acc[r][c] = 0.f;
    }

    for (int j = 0; j <= qb; ++j) {
        __syncthreads();

        for (int i = tid; i < 1024; i += 256) {
            int n = i >> 4, f = i & 15;
            float4 kv = *(const float4*)(Kp + (size_t)(j * 64 + n) * HD + f * 4);
            int go = (((n >> 2) ^ f) << 2) + (n & 3);
            Kt[(f * 4 + 0) * 64 + go] = kv.x;
            Kt[(f * 4 + 1) * 64 + go] = kv.y;
            Kt[(f * 4 + 2) * 64 + go] = kv.z;
            Kt[(f * 4 + 3) * 64 + go] = kv.w;
            *(float4*)&Vs[n * 64 + f * 4] =
                *(const float4*)(Vp + (size_t)(j * 64 + n) * HD + f * 4);
        }
        __syncthreads();

        float s[4][4];
#pragma unroll
        for (int r = 0; r < 4; ++r)
#pragma unroll
            for (int c = 0; c < 4; ++c) s[r][c] = 0.f;

#pragma unroll
        for (int k = 0; k < 64; k += 4) {
            float q4[4][4], k4[4][4];
#pragma unroll
            for (int r = 0; r < 4; ++r)
                *(float4*)&q4[r][0] = *(const float4*)&Qs[(ty * 4 + r) * 64 + k];
#pragma unroll
            for (int t = 0; t < 4; ++t) {
                int kk = k + t;
                *(float4*)&k4[t][0] =
                    *(const float4*)&Kt[kk * 64 + ((tx ^ (kk >> 2)) << 2)];
            }
#pragma unroll
            for (int r = 0; r < 4; ++r)
#pragma unroll
                for (int t = 0; t < 4; ++t)
#pragma unroll
                    for (int c = 0; c < 4; ++c)
                        s[r][c] = fmaf(q4[r][t], k4[t][c], s[r][c]);
        }

        if (j == qb) {
#pragma unroll
            for (int r = 0; r < 4; ++r)
#pragma unroll
                for (int c = 0; c < 4; ++c)
                    if (tx * 4 + c > ty * 4 + r) s[r][c] = -1e30f;
        }

        __syncthreads();

#pragma unroll
        for (int r = 0; r < 4; ++r) {
            float rm = fmaxf(fmaxf(s[r][0], s[r][1]), fmaxf(s[r][2], s[r][3]));
#pragma unroll
            for (int off = 8; off >= 1; off >>= 1)
                rm = fmaxf(rm, __shfl_xor_sync(0xffffffffu, rm, off, 16));
            float mnew  = fmaxf(mi[r], rm);
            float alpha = __expf(mi[r] - mnew);
            mi[r] = mnew;

            float ls = 0.f;
#pragma unroll
            for (int c = 0; c < 4; ++c) {
                s[r][c] = __expf(s[r][c] - mnew);
                ls += s[r][c];
            }
#pragma unroll
            for (int off = 8; off >= 1; off >>= 1)
                ls += __shfl_xor_sync(0xffffffffu, ls, off, 16);
            li[r] = li[r] * alpha + ls;
#pragma unroll
            for (int c = 0; c < 4; ++c) acc[r][c] *= alpha;

            *(float4*)&Kt[(ty * 4 + r) * 64 + tx * 4] = *(float4*)&s[r][0];
        }
        __syncthreads();

#pragma unroll
        for (int k = 0; k < 64; k += 4) {
            float p4[4][4], v4[4][4];
#pragma unroll
            for (int r = 0; r < 4; ++r)
                *(float4*)&p4[r][0] = *(const float4*)&Kt[(ty * 4 + r) * 64 + k];
#pragma unroll
            for (int t = 0; t < 4; ++t)
                *(float4*)&v4[t][0] = *(const float4*)&Vs[(k + t) * 64 + tx * 4];
#pragma unroll
            for (int r = 0; r < 4; ++r)
#pragma unroll
                for (int t = 0; t < 4; ++t)
#pragma unroll
                    for (int c = 0; c < 4; ++c)
                        acc[r][c] = fmaf(p4[r][t], v4[t][c], acc[r][c]);
        }
    }

#pragma unroll
    for (int r = 0; r < 4; ++r) {
        float inv = 1.f / li[r];
        float4 o = make_float4(acc[r][0] * inv, acc[r][1] * inv,
                               acc[r][2] * inv, acc[r][3] * inv);
        *(float4*)&g_attn[((size_t)b * SEQ + q0 + ty * 4 + r) * EMB + h * HD + tx * 4] = o;
    }
}

// ---------------------------------------------------------------------------
extern "C" void kernel_launch(void* const* d_in, const int* in_sizes, int n_in,
                              void* d_out, int out_size)
{
    const float* x  = (const float*)d_in[0];
    const float* Wq = (const float*)d_in[1];
    const float* Wk = (const float*)d_in[2];
    const float* Wv = (const float*)d_in[3];
    const float* Wp = (const float*)d_in[4];
    const float* bp = (const float*)d_in[5];
    float* out = (float*)d_out;

    cudaFuncSetAttribute(hmma_gemm,
                         cudaFuncAttributeMaxDynamicSharedMemorySize, GEMM_SMEM);

    const int n4x = (BATCH * SEQ * EMB) / 4;   // 2,097,152 float4s (divisible by 256)

    // Split inputs to bf16 hi/lo (device globals touched only in device code)
    split_x<<<n4x / 256, 256>>>(x);
    conv_wqkv<<<3 * NH * HD, 256>>>(Wq, Wk, Wv);
    conv_wp<<<dim3(EMB / 32, EMB / 32), dim3(32, 8)>>>(Wp);

    // QKV: [8192 x 1024] x [1024 x 3072] -> scatter into g_q/g_k/g_v
    hmma_gemm<<<dim3(BATCH * SEQ / 128, 3 * NH * HD / 64), 256, GEMM_SMEM>>>(
        nullptr, nullptr, 0);

    // Attention (fp32, verified)
    attn_kernel<<<dim3(SEQ / 64, NH, BATCH), 256>>>();

    // Split attention output, then proj: [8192 x 1024] x [1024 x 1024] + bias
    split_attn<<<n4x / 256, 256>>>();
    hmma_gemm<<<dim3(BATCH * SEQ / 128, EMB / 64), 256, GEMM_SMEM>>>(bp, out, 1);
}

// round 11
// speedup vs baseline: 2.4360x; 1.6032x over previous
#include <cuda_runtime.h>
#include <cuda_bf16.h>
#include <cstdint>

#define BATCH 4
#define SEQ   2048
#define EMB   1024
#define NH    16
#define HD    64

// ---------------------------------------------------------------------------
// Scratch (__device__ globals; referenced ONLY from device code)
// ---------------------------------------------------------------------------
__device__ __align__(16) __nv_bfloat16 g_xhi[(size_t)BATCH * SEQ * EMB];
__device__ __align__(16) __nv_bfloat16 g_xlo[(size_t)BATCH * SEQ * EMB];
__device__ __align__(16) __nv_bfloat16 g_ahi[(size_t)BATCH * SEQ * EMB];   // attn out hi
__device__ __align__(16) __nv_bfloat16 g_alo[(size_t)BATCH * SEQ * EMB];   // attn out lo
__device__ __align__(16) __nv_bfloat16 g_qhi[(size_t)BATCH * NH * SEQ * HD]; // [B,H,S,64], pre-scaled
__device__ __align__(16) __nv_bfloat16 g_qlo[(size_t)BATCH * NH * SEQ * HD];
__device__ __align__(16) __nv_bfloat16 g_khi[(size_t)BATCH * NH * SEQ * HD]; // [B,H,S,64]
__device__ __align__(16) __nv_bfloat16 g_klo[(size_t)BATCH * NH * SEQ * HD];
__device__ __align__(16) __nv_bfloat16 g_vthi[(size_t)BATCH * NH * HD * SEQ]; // [B,H,64,S] (V^T)
__device__ __align__(16) __nv_bfloat16 g_vtlo[(size_t)BATCH * NH * HD * SEQ];
__device__ __align__(16) __nv_bfloat16 g_bqkv_hi[(size_t)3 * NH * HD * EMB]; // [3072][1024]
__device__ __align__(16) __nv_bfloat16 g_bqkv_lo[(size_t)3 * NH * HD * EMB];
__device__ __align__(16) __nv_bfloat16 g_bp_hi[(size_t)EMB * EMB];           // Wp^T [1024][1024]
__device__ __align__(16) __nv_bfloat16 g_bp_lo[(size_t)EMB * EMB];

// ---------------------------------------------------------------------------
// Helpers
// ---------------------------------------------------------------------------
__device__ __forceinline__ void split1(float v, __nv_bfloat16& h, __nv_bfloat16& l) {
    h = __float2bfloat16(v);
    l = __float2bfloat16(v - __bfloat162float(h));
}
__device__ __forceinline__ void split2(float x, float y, uint32_t& hp, uint32_t& lp) {
    __nv_bfloat16 hx = __float2bfloat16(x), hy = __float2bfloat16(y);
    __nv_bfloat16 lx = __float2bfloat16(x - __bfloat162float(hx));
    __nv_bfloat16 ly = __float2bfloat16(y - __bfloat162float(hy));
    hp = (uint32_t)__bfloat16_as_ushort(hx) | ((uint32_t)__bfloat16_as_ushort(hy) << 16);
    lp = (uint32_t)__bfloat16_as_ushort(lx) | ((uint32_t)__bfloat16_as_ushort(ly) << 16);
}
__device__ __forceinline__ uint32_t smem_u32(const void* p) {
    uint32_t a;
    asm("{ .reg .u64 t; cvta.to.shared.u64 t, %1; cvt.u32.u64 %0, t; }" : "=r"(a) : "l"(p));
    return a;
}
__device__ __forceinline__ void ldsm_x4(uint32_t* r, uint32_t addr) {
    asm volatile("ldmatrix.sync.aligned.m8n8.x4.shared.b16 {%0,%1,%2,%3}, [%4];"
        : "=r"(r[0]), "=r"(r[1]), "=r"(r[2]), "=r"(r[3]) : "r"(addr));
}
__device__ __forceinline__ void mma_bf16(float* c, const uint32_t* a,
                                         uint32_t b0, uint32_t b1) {
    asm volatile("mma.sync.aligned.m16n8k16.row.col.f32.bf16.bf16.f32 "
        "{%0,%1,%2,%3}, {%4,%5,%6,%7}, {%8,%9}, {%0,%1,%2,%3};"
        : "+f"(c[0]), "+f"(c[1]), "+f"(c[2]), "+f"(c[3])
        : "r"(a[0]), "r"(a[1]), "r"(a[2]), "r"(a[3]), "r"(b0), "r"(b1));
}

union BF4 { __nv_bfloat16 b[4]; uint2 u; };

// ---------------------------------------------------------------------------
// Conversions
// ---------------------------------------------------------------------------
__global__ void split_x(const float* __restrict__ in)   // x -> g_xhi/g_xlo
{
    int i = blockIdx.x * 256 + threadIdx.x;
    float4 v = ((const float4*)in)[i];
    BF4 hh, ll;
    split1(v.x, hh.b[0], ll.b[0]); split1(v.y, hh.b[1], ll.b[1]);
    split1(v.z, hh.b[2], ll.b[2]); split1(v.w, hh.b[3], ll.b[3]);
    ((uint2*)g_xhi)[i] = hh.u;
    ((uint2*)g_xlo)[i] = ll.u;
}

__global__ void conv_wqkv(const float* __restrict__ Wq,
                          const float* __restrict__ Wk,
                          const float* __restrict__ Wv)
{
    int n = blockIdx.x;
    int which = n >> 10, h = (n >> 6) & 15, d = n & 63;
    const float* W = (which == 0) ? Wq : (which == 1) ? Wk : Wv;
    for (int e = threadIdx.x; e < EMB; e += 256) {
        float v = W[((size_t)h * EMB + e) * HD + d];
        __nv_bfloat16 hh, ll;
        split1(v, hh, ll);
        g_bqkv_hi[(size_t)n * EMB + e] = hh;
        g_bqkv_lo[(size_t)n * EMB + e] = ll;
    }
}

__global__ void conv_wp(const float* __restrict__ Wp)
{
    __shared__ float t[32][33];
    int n0 = blockIdx.x * 32, k0 = blockIdx.y * 32;
    for (int r = threadIdx.y; r < 32; r += 8)
        t[r][threadIdx.x] = Wp[(size_t)(k0 + r) * EMB + n0 + threadIdx.x];
    __syncthreads();
    for (int r = threadIdx.y; r < 32; r += 8) {
        float v = t[threadIdx.x][r];
        __nv_bfloat16 hh, ll;
        split1(v, hh, ll);
        g_bp_hi[(size_t)(n0 + r) * EMB + k0 + threadIdx.x] = hh;
        g_bp_lo[(size_t)(n0 + r) * EMB + k0 + threadIdx.x] = ll;
    }
}

// ---------------------------------------------------------------------------
// Split-precision bf16 HMMA GEMM (validated R9). D[128x64] = A[128x1024]*B^T.
//  mode 0: A=x, B=Wqkv; epilogue splits into g_q*/g_k* and transposed g_vt*.
//  mode 1: A=attn out (g_ahi/lo), B=Wp^T; +bias, fp32 row-major out.
// ---------------------------------------------------------------------------
#define RS 72
#define OFF_AH 0
#define OFF_AL (128 * RS)
#define OFF_BH (256 * RS)
#define OFF_BL (256 * RS + 64 * RS)
#define GEMM_SMEM ((256 * RS + 128 * RS) * 2)

__global__ __launch_bounds__(256) void hmma_gemm(
    const float* __restrict__ bias,
    float* __restrict__ outp, int mode)
{
    extern __shared__ __align__(16) __nv_bfloat16 sm[];
    const int tid = threadIdx.x, wid = tid >> 5, lane = tid & 31;
    const int wm = wid >> 1, wn = wid & 1;
    const int m0 = blockIdx.x * 128, n0 = blockIdx.y * 64;

    const __nv_bfloat16* __restrict__ Ahi = (mode == 0) ? g_xhi : g_ahi;
    const __nv_bfloat16* __restrict__ Alo = (mode == 0) ? g_xlo : g_alo;
    const __nv_bfloat16* __restrict__ Bhi = (mode == 0) ? g_bqkv_hi : g_bp_hi;
    const __nv_bfloat16* __restrict__ Blo = (mode == 0) ? g_bqkv_lo : g_bp_lo;

    float acc[2][4][4];
#pragma unroll
    for (int mt = 0; mt < 2; ++mt)
#pragma unroll
        for (int nt = 0; nt < 4; ++nt)
#pragma unroll
            for (int i = 0; i < 4; ++i) acc[mt][nt][i] = 0.f;

    const uint32_t a_row = wm * 32 + ((lane >> 3) & 1) * 8 + (lane & 7);
    const uint32_t a_kof = ((lane >> 4) & 1) * 8;
    const uint32_t b_row = wn * 32 + ((lane >> 4) & 1) * 8 + (lane & 7);
    const uint32_t b_kof = ((lane >> 3) & 1) * 8;
    const uint32_t sb = smem_u32(sm);
    const uint32_t aA = sb + (a_row * RS + a_kof) * 2;
    const uint32_t aB = sb + (b_row * RS + b_kof) * 2;

    for (int kt = 0; kt < 16; ++kt) {
        __syncthreads();
#pragma unroll
        for (int t = 0; t < 4; ++t) {
            int i = tid + t * 256;
            int row = i >> 3, g = i & 7;
            size_t src = (size_t)(m0 + row) * 128 + kt * 8 + g;
            uint32_t d = row * RS + g * 8;
            *(uint4*)(sm + OFF_AH + d) = ((const uint4*)Ahi)[src];
            *(uint4*)(sm + OFF_AL + d) = ((const uint4*)Alo)[src];
        }
#pragma unroll
        for (int t = 0; t < 2; ++t) {
            int i = tid + t * 256;
            int row = i >> 3, g = i & 7;
            size_t src = (size_t)(n0 + row) * 128 + kt * 8 + g;
            uint32_t d = row * RS + g * 8;
            *(uint4*)(sm + OFF_BH + d) = ((const uint4*)Bhi)[src];
            *(uint4*)(sm + OFF_BL + d) = ((const uint4*)Blo)[src];
        }
        __syncthreads();

#pragma unroll
        for (int ks = 0; ks < 4; ++ks) {
            uint32_t aH[2][4], aL[2][4], bH[2][4], bL[2][4];
#pragma unroll
            for (int mt = 0; mt < 2; ++mt) {
                uint32_t off = mt * (16 * RS * 2) + ks * 32;
                ldsm_x4(aH[mt], aA + OFF_AH * 2 + off);
                ldsm_x4(aL[mt], aA + OFF_AL * 2 + off);
            }
#pragma unroll
            for (int g16 = 0; g16 < 2; ++g16) {
                uint32_t off = g16 * (16 * RS * 2) + ks * 32;
                ldsm_x4(bH[g16], aB + OFF_BH * 2 + off);
                ldsm_x4(bL[g16], aB + OFF_BL * 2 + off);
            }
#pragma unroll
            for (int mt = 0; mt < 2; ++mt)
#pragma unroll
                for (int nt = 0; nt < 4; ++nt) {
                    uint32_t h0 = bH[nt >> 1][(nt & 1) * 2], h1 = bH[nt >> 1][(nt & 1) * 2 + 1];
                    uint32_t l0 = bL[nt >> 1][(nt & 1) * 2], l1 = bL[nt >> 1][(nt & 1) * 2 + 1];
                    mma_bf16(acc[mt][nt], aH[mt], h0, h1);
                    mma_bf16(acc[mt][nt], aH[mt], l0, l1);
                    mma_bf16(acc[mt][nt], aL[mt], h0, h1);
                }
        }
    }

    const int gr = lane >> 2, cp = (lane & 3) * 2;
#pragma unroll
    for (int mt = 0; mt < 2; ++mt)
#pragma unroll
        for (int nt = 0; nt < 4; ++nt) {
            int ng = n0 + wn * 32 + nt * 8 + cp;
#pragma unroll
            for (int half = 0; half < 2; ++half) {
                int m = m0 + wm * 32 + mt * 16 + gr + half * 8;
                float2 v = make_float2(acc[mt][nt][half * 2], acc[mt][nt][half * 2 + 1]);
                if (mode == 1) {
                    v.x += bias[ng]; v.y += bias[ng + 1];
                    *(float2*)(outp + (size_t)m * EMB + ng) = v;
                } else {
                    int which = ng >> 10, h = (ng >> 6) & 15, d = ng & 63;
                    int b = m >> 11, s = m & 2047;
                    size_t bh = (size_t)b * NH + h;
                    if (which == 0) {            // q: fold softmax scale, split
                        uint32_t ph, pl;
                        split2(v.x * 0.125f, v.y * 0.125f, ph, pl);
                        size_t idx = (bh * SEQ + s) * HD + d;
                        *(uint32_t*)&g_qhi[idx] = ph;
                        *(uint32_t*)&g_qlo[idx] = pl;
                    } else if (which == 1) {     // k: split
                        uint32_t ph, pl;
                        split2(v.x, v.y, ph, pl);
                        size_t idx = (bh * SEQ + s) * HD + d;
                        *(uint32_t*)&g_khi[idx] = ph;
                        *(uint32_t*)&g_klo[idx] = pl;
                    } else {                     // v: split + transpose [d][s]
                        __nv_bfloat16 hx, lx, hy, ly;
                        split1(v.x, hx, lx); split1(v.y, hy, ly);
                        size_t i0 = (bh * HD + d) * SEQ + s;
                        g_vthi[i0] = hx;       g_vtlo[i0] = lx;
                        g_vthi[i0 + SEQ] = hy; g_vtlo[i0 + SEQ] = ly;
                    }
                }
            }
        }
}

// ---------------------------------------------------------------------------
// HMMA causal flash attention (split-precision bf16, fp32 accum).
// grid (S/64, H, B), 128 threads = 4 warps; warp w owns q-rows w*16..w*16+15
// for all 64 keys -> softmax row stats reduce within a 4-lane shfl group.
// Writes g_ahi/g_alo directly (no separate split pass).
// ---------------------------------------------------------------------------
#define ARS 72
#define A_QH 0
#define A_QL 4608
#define A_KH 9216
#define A_KL 13824
#define A_VH 18432
#define A_VL 23040
#define ATTN_SMEM (27648 * 2)   // 55296 B

__global__ __launch_bounds__(128) void attn_hmma()
{
    extern __shared__ __align__(16) __nv_bfloat16 sh[];
    const int tid = threadIdx.x, warp = tid >> 5, lane = tid & 31;
    const int qb = blockIdx.x, h = blockIdx.y, b = blockIdx.z;
    const size_t bh = (size_t)b * NH + h;
    const int q0 = qb * 64;
    const int g = lane >> 2, tg = lane & 3;

    // ldmatrix lane addressing (layouts validated by the R9 GEMM pass)
    const int a_row = warp * 16 + ((lane >> 3) & 1) * 8 + (lane & 7);
    const int a_kof = ((lane >> 4) & 1) * 8;
    const int b_sub = ((lane >> 4) & 1) * 8 + (lane & 7);
    const int b_kof = ((lane >> 3) & 1) * 8;
    const uint32_t sb = smem_u32(sh);
    const uint32_t adrQH = sb + (A_QH + a_row * ARS + a_kof) * 2;
    const uint32_t adrQL = sb + (A_QL + a_row * ARS + a_kof) * 2;
    const uint32_t adrKH = sb + (A_KH + b_sub * ARS + b_kof) * 2;
    const uint32_t adrKL = sb + (A_KL + b_sub * ARS + b_kof) * 2;
    const uint32_t adrVH = sb + (A_VH + b_sub * ARS + b_kof) * 2;
    const uint32_t adrVL = sb + (A_VL + b_sub * ARS + b_kof) * 2;

    // Stage Q tile once (rows = 8 uint4 data, stride 9 uint4)
    {
        const uint4* qh4 = (const uint4*)g_qhi + (bh * SEQ + q0) * 8;
        const uint4* ql4 = (const uint4*)g_qlo + (bh * SEQ + q0) * 8;
        uint4* dh = (uint4*)(sh + A_QH);
        uint4* dl = (uint4*)(sh + A_QL);
        for (int i = tid; i < 512; i += 128) {
            int row = i >> 3, c = i & 7;
            dh[row * 9 + c] = qh4[row * 8 + c];
            dl[row * 9 + c] = ql4[row * 8 + c];
        }
    }

    float o[8][4];
#pragma unroll
    for (int nt = 0; nt < 8; ++nt)
#pragma unroll
        for (int i = 0; i < 4; ++i) o[nt][i] = 0.f;
    float mi0 = -1e30f, mi1 = -1e30f, li0 = 0.f, li1 = 0.f;

    for (int j = 0; j <= qb; ++j) {
        __syncthreads();   // prior tile's smem reads complete (covers Q stage too)
        {
            const uint4* kh4 = (const uint4*)g_khi + (bh * SEQ + j * 64) * 8;
            const uint4* kl4 = (const uint4*)g_klo + (bh * SEQ + j * 64) * 8;
            const uint4* vh4 = (const uint4*)g_vthi + bh * HD * 256 + j * 8;  // row d: *256
            const uint4* vl4 = (const uint4*)g_vtlo + bh * HD * 256 + j * 8;
            uint4* dkh = (uint4*)(sh + A_KH);
            uint4* dkl = (uint4*)(sh + A_KL);
            uint4* dvh = (uint4*)(sh + A_VH);
            uint4* dvl = (uint4*)(sh + A_VL);
            for (int i = tid; i < 512; i += 128) {
                int row = i >> 3, c = i & 7;
                dkh[row * 9 + c] = kh4[row * 8 + c];
                dkl[row * 9 + c] = kl4[row * 8 + c];
                dvh[row * 9 + c] = vh4[row * 256 + c];
                dvl[row * 9 + c] = vl4[row * 256 + c];
            }
        }
        __syncthreads();

        // ---- S = Q K^T (3-MMA split) ----
        float s[8][4];
#pragma unroll
        for (int nt = 0; nt < 8; ++nt)
#pragma unroll
            for (int i = 0; i < 4; ++i) s[nt][i] = 0.f;

#pragma unroll
        for (int ks = 0; ks < 4; ++ks) {
            uint32_t qh[4], ql[4];
            ldsm_x4(qh, adrQH + ks * 32);
            ldsm_x4(ql, adrQL + ks * 32);
#pragma unroll
            for (int g16 = 0; g16 < 4; ++g16) {
                uint32_t kh[4], kl[4];
                uint32_t go = g16 * (16 * ARS * 2);
                ldsm_x4(kh, adrKH + go + ks * 32);
                ldsm_x4(kl, adrKL + go + ks * 32);
#pragma unroll
                for (int sn = 0; sn < 2; ++sn) {
                    int nt = g16 * 2 + sn;
                    mma_bf16(s[nt], qh, kh[sn * 2], kh[sn * 2 + 1]);
                    mma_bf16(s[nt], qh, kl[sn * 2], kl[sn * 2 + 1]);
                    mma_bf16(s[nt], ql, kh[sn * 2], kh[sn * 2 + 1]);
                }
            }
        }

        // ---- causal mask (diagonal tile only) ----
        if (j == qb) {
            int r0 = warp * 16 + g, r1 = r0 + 8;
#pragma unroll
            for (int nt = 0; nt < 8; ++nt) {
                int c0 = nt * 8 + tg * 2;
                if (c0 > r0)     s[nt][0] = -1e30f;
                if (c0 + 1 > r0) s[nt][1] = -1e30f;
                if (c0 > r1)     s[nt][2] = -1e30f;
                if (c0 + 1 > r1) s[nt][3] = -1e30f;
            }
        }

        // ---- online softmax (rows r0, r1; reduce across 4-lane group) ----
        float mx0 = -1e30f, mx1 = -1e30f;
#pragma unroll
        for (int nt = 0; nt < 8; ++nt) {
            mx0 = fmaxf(mx0, fmaxf(s[nt][0], s[nt][1]));
            mx1 = fmaxf(mx1, fmaxf(s[nt][2], s[nt][3]));
        }
        mx0 = fmaxf(mx0, __shfl_xor_sync(0xffffffffu, mx0, 1));
        mx0 = fmaxf(mx0, __shfl_xor_sync(0xffffffffu, mx0, 2));
        mx1 = fmaxf(mx1, __shfl_xor_sync(0xffffffffu, mx1, 1));
        mx1 = fmaxf(mx1, __shfl_xor_sync(0xffffffffu, mx1, 2));
        float mn0 = fmaxf(mi0, mx0), mn1 = fmaxf(mi1, mx1);
        float al0 = __expf(mi0 - mn0), al1 = __expf(mi1 - mn1);
        mi0 = mn0; mi1 = mn1;
        float ls0 = 0.f, ls1 = 0.f;
#pragma unroll
        for (int nt = 0; nt < 8; ++nt) {
            s[nt][0] = __expf(s[nt][0] - mn0); ls0 += s[nt][0];
            s[nt][1] = __expf(s[nt][1] - mn0); ls0 += s[nt][1];
            s[nt][2] = __expf(s[nt][2] - mn1); ls1 += s[nt][2];
            s[nt][3] = __expf(s[nt][3] - mn1); ls1 += s[nt][3];
        }
        ls0 += __shfl_xor_sync(0xffffffffu, ls0, 1);
        ls0 += __shfl_xor_sync(0xffffffffu, ls0, 2);
        ls1 += __shfl_xor_sync(0xffffffffu, ls1, 1);
        ls1 += __shfl_xor_sync(0xffffffffu, ls1, 2);
        li0 = li0 * al0 + ls0;
        li1 = li1 * al1 + ls1;
#pragma unroll
        for (int nt = 0; nt < 8; ++nt) {
            o[nt][0] *= al0; o[nt][1] *= al0;
            o[nt][2] *= al1; o[nt][3] *= al1;
        }

        // ---- P -> hi/lo A-fragments (C-frag -> A-frag identity mapping) ----
        uint32_t pah[4][4], pal[4][4];
#pragma unroll
        for (int kc = 0; kc < 4; ++kc) {
            split2(s[2 * kc][0],     s[2 * kc][1],     pah[kc][0], pal[kc][0]);
            split2(s[2 * kc][2],     s[2 * kc][3],     pah[kc][1], pal[kc][1]);
            split2(s[2 * kc + 1][0], s[2 * kc + 1][1], pah[kc][2], pal[kc][2]);
            split2(s[2 * kc + 1][2], s[2 * kc + 1][3], pah[kc][3], pal[kc][3]);
        }

        // ---- O += P V  (V^T tiles as B operand) ----
#pragma unroll
        for (int g16 = 0; g16 < 4; ++g16) {
            uint32_t go = g16 * (16 * ARS * 2);
#pragma unroll
            for (int kc = 0; kc < 4; ++kc) {
                uint32_t vh[4], vl[4];
                ldsm_x4(vh, adrVH + go + kc * 32);
                ldsm_x4(vl, adrVL + go + kc * 32);
#pragma unroll
                for (int sn = 0; sn < 2; ++sn) {
                    int nt = g16 * 2 + sn;
                    mma_bf16(o[nt], pah[kc], vh[sn * 2], vh[sn * 2 + 1]);
                    mma_bf16(o[nt], pah[kc], vl[sn * 2], vl[sn * 2 + 1]);
                    mma_bf16(o[nt], pal[kc], vh[sn * 2], vh[sn * 2 + 1]);
                }
            }
        }
    }

    // ---- epilogue: normalize + split-store to g_ahi/g_alo [B,S,E] ----
    float inv0 = 1.f / li0, inv1 = 1.f / li1;
    int r0 = q0 + warp * 16 + g;
    size_t base0 = ((size_t)b * SEQ + r0) * EMB + h * HD;
    size_t base1 = base0 + (size_t)8 * EMB;
#pragma unroll
    for (int nt = 0; nt < 8; ++nt) {
        int d = nt * 8 + tg * 2;
        uint32_t ph, pl;
        split2(o[nt][0] * inv0, o[nt][1] * inv0, ph, pl);
        *(uint32_t*)&g_ahi[base0 + d] = ph;
        *(uint32_t*)&g_alo[base0 + d] = pl;
        split2(o[nt][2] * inv1, o[nt][3] * inv1, ph, pl);
        *(uint32_t*)&g_ahi[base1 + d] = ph;
        *(uint32_t*)&g_alo[base1 + d] = pl;
    }
}

// ---------------------------------------------------------------------------
extern "C" void kernel_launch(void* const* d_in, const int* in_sizes, int n_in,
                              void* d_out, int out_size)
{
    const float* x  = (const float*)d_in[0];
    const float* Wq = (const float*)d_in[1];
    const float* Wk = (const float*)d_in[2];
    const float* Wv = (const float*)d_in[3];
    const float* Wp = (const float*)d_in[4];
    const float* bp = (const float*)d_in[5];
    float* out = (float*)d_out;

    cudaFuncSetAttribute(hmma_gemm,
                         cudaFuncAttributeMaxDynamicSharedMemorySize, GEMM_SMEM);
    cudaFuncSetAttribute(attn_hmma,
                         cudaFuncAttributeMaxDynamicSharedMemorySize, ATTN_SMEM);

    const int n4x = (BATCH * SEQ * EMB) / 4;

    split_x<<<n4x / 256, 256>>>(x);
    conv_wqkv<<<3 * NH * HD, 256>>>(Wq, Wk, Wv);
    conv_wp<<<dim3(EMB / 32, EMB / 32), dim3(32, 8)>>>(Wp);

    // QKV projections -> bf16 hi/lo q, k, v^T
    hmma_gemm<<<dim3(BATCH * SEQ / 128, 3 * NH * HD / 64), 256, GEMM_SMEM>>>(
        nullptr, nullptr, 0);

    // HMMA flash attention -> g_ahi/g_alo
    attn_hmma<<<dim3(SEQ / 64, NH, BATCH), 128, ATTN_SMEM>>>();

    // Output projection
    hmma_gemm<<<dim3(BATCH * SEQ / 128, EMB / 64), 256, GEMM_SMEM>>>(bp, out, 1);
}